// round 11
// baseline (speedup 1.0000x reference)
#include <cuda_runtime.h>

// ---------------------------------------------------------------------------
// O(2) FullTensorProduct — half-row CTAs, 8 CTAs/SM, __stwt stores.
//
// Identical to R8/R10 best (86.2us) except stores use st.global.wt
// (write-through) instead of st.global.cs (evict-first). R9 proved store
// cache policy matters in graph-replay steady state (+4us for write-back
// due to L2 dirty-drain); .wt minimizes dirty residency harder than .cs.
// Single-variable test; if neutral or worse, R8 (.cs) is the final kernel.
//
// Evidence trail:
//   R3  2048x256, 3 waves, .cs        -> 88.3us
//   R4  per-element tiles             -> 114.8us (overhead-bound)
//   R5  single wave, 16 CTA/SM        -> 100.4us (spread exposure)
//   R6  single wave, 2 rows/CTA       -> 98.8us
//   R7  half-row CTAs, 7/SM, .cs      -> 86.4us
//   R8  half-row CTAs, 8/SM, .cs      -> 86.2us (reproduced R10)
//   R9  R8 with default write-back    -> 90.2us (L2 dirty-drain in replay)
// ---------------------------------------------------------------------------

namespace {

constexpr int DIM1    = 448;
constexpr int DIM2    = 160;
constexpr int ROW_OUT = 71680;
constexpr float R2f   = 0.70710678118654752440f;   // 1/sqrt(2)
constexpr float SQ2f  = 1.41421356237309504880f;   // sqrt(2)

__device__ __forceinline__ void st4(float* base, int idx4, float4 v) {
    __stwt(reinterpret_cast<float4*>(base) + idx4, v);   // st.global.wt STG.128
}

// kind A: (m=0)x(m=0) -> scalar. 512 float4 total; this CTA does 256.
__device__ __forceinline__ void chunkA(float* o, const float* x1, const float* x2,
                                       int t, int h) {
    int idx = h * 256 + t;               // 0..511
    int u   = idx >> 3;
    int v   = (idx & 7) << 2;
    float a = x1[u];
    st4(o, idx, make_float4(a * x2[v], a * x2[v + 1], a * x2[v + 2], a * x2[v + 3]));
}

// kind B: (m=0)x(m>0). 1024 float4 total; this CTA does 512.
__device__ __forceinline__ void chunkB(float* o, const float* x1, const float* x2,
                                       int t, int h) {
#pragma unroll
    for (int it = 0; it < 2; ++it) {
        int idx = (h * 2 + it) * 256 + t;    // 0..1023
        int u   = idx >> 4;
        int j   = (idx & 15) << 2;
        float a = SQ2f * x1[u];
        st4(o, idx, make_float4(a * x2[j], a * x2[j + 1], a * x2[j + 2], a * x2[j + 3]));
    }
}

// kind C: (m>0)x(m=0). 1024 float4 total; this CTA does 512.
__device__ __forceinline__ void chunkC(float* o, const float* x1, const float* x2,
                                       int t, int h) {
#pragma unroll
    for (int it = 0; it < 2; ++it) {
        int idx = (h * 2 + it) * 256 + t;
        int u   = idx >> 4;
        int j   = (idx & 15) << 1;
        float a = SQ2f * x1[2 * u];
        float b = SQ2f * x1[2 * u + 1];
        float p = x2[j], q = x2[j + 1];
        st4(o, idx, make_float4(a * p, b * p, a * q, b * q));
    }
}

// kind D: (m)x(m) -> m=0. 512 float4 total; this CTA does 256.
template<bool PLUS>
__device__ __forceinline__ void chunkD(float* o, const float* x1, const float* x2,
                                       int t, int h) {
    int idx = h * 256 + t;
    int u   = idx >> 3;
    int j   = idx & 7;
    float c1 = x1[2 * u], s1 = x1[2 * u + 1];
    float r[4];
#pragma unroll
    for (int k = 0; k < 4; ++k) {
        float c2 = x2[8 * j + 2 * k];
        float s2 = x2[8 * j + 2 * k + 1];
        r[k] = PLUS ? R2f * fmaf(c1, c2,  s1 * s2)
                    : R2f * fmaf(s1, c2, -(c1 * s2));
    }
    st4(o, idx, make_float4(r[0], r[1], r[2], r[3]));
}

// kind E: (m1)x(m2) -> 2-dim irrep. 1024 float4 total; this CTA does 512.
template<int SA, int SSC, int SCS>
__device__ __forceinline__ void chunkE(float* o, const float* x1, const float* x2,
                                       int t, int h) {
#pragma unroll
    for (int it = 0; it < 2; ++it) {
        int idx = (h * 2 + it) * 256 + t;
        int u   = idx >> 4;
        int j   = idx & 15;
        float c1 = x1[2 * u], s1 = x1[2 * u + 1];
        float4 r;
        {
            float c2 = x2[4 * j], s2 = x2[4 * j + 1];
            r.x = fmaf(c1, c2, float(SA) * (s1 * s2));
            r.y = fmaf(float(SSC) * s1, c2, float(SCS) * (c1 * s2));
        }
        {
            float c2 = x2[4 * j + 2], s2 = x2[4 * j + 3];
            r.z = fmaf(c1, c2, float(SA) * (s1 * s2));
            r.w = fmaf(float(SSC) * s1, c2, float(SCS) * (c1 * s2));
        }
        st4(o, idx, r);
    }
}

__global__ void __launch_bounds__(256, 8) tp_kernel(const float* __restrict__ in1,
                                                    const float* __restrict__ in2,
                                                    float* __restrict__ out) {
    __shared__ __align__(16) float s1[DIM1];
    __shared__ __align__(16) float s2[DIM2];

    const int t = threadIdx.x;                 // 0..255
    const unsigned bid = blockIdx.x;           // 0..4095
    const size_t b = bid >> 1;                 // batch row
    const int    h = bid & 1;                  // which half of the row

    const float4* r1 = reinterpret_cast<const float4*>(in1 + b * DIM1);
    const float4* r2 = reinterpret_cast<const float4*>(in2 + b * DIM2);
    if (t < 112) reinterpret_cast<float4*>(s1)[t] = r1[t];
    if (t < 40)  reinterpret_cast<float4*>(s2)[t] = r2[t];
    __syncthreads();

    float* o = out + b * (size_t)ROW_OUT;

    const float* x1m0 = s1;          // [0,64)
    const float* x1m1 = s1 + 64;     // [64,192)
    const float* x1m2 = s1 + 192;    // [192,320)
    const float* x1m3 = s1 + 320;    // [320,448)
    const float* x2m0 = s2;          // [0,32)
    const float* x2m1 = s2 + 32;     // [32,96)
    const float* x2m2 = s2 + 96;     // [96,160)

    // Output chunks in INV (irrep-sorted, stable) order; offsets in floats.
    chunkA           (o + 0,     x1m0, x2m0, t, h);   // 0x0 -> 0+
    chunkD<true >    (o + 2048,  x1m1, x2m1, t, h);   // 1x1 -> 0+
    chunkD<true >    (o + 4096,  x1m2, x2m2, t, h);   // 2x2 -> 0+
    chunkD<false>    (o + 6144,  x1m1, x2m1, t, h);   // 1x1 -> 0-
    chunkD<false>    (o + 8192,  x1m2, x2m2, t, h);   // 2x2 -> 0-
    chunkB           (o + 10240, x1m0, x2m1, t, h);   // 0x1 -> 1
    chunkC           (o + 14336, x1m1, x2m0, t, h);   // 1x0 -> 1
    chunkE< 1,-1, 1> (o + 18432, x1m1, x2m2, t, h);   // 1x2 -> 1 (diff, sgn=-1)
    chunkE< 1, 1,-1> (o + 22528, x1m2, x2m1, t, h);   // 2x1 -> 1 (diff, sgn=+1)
    chunkE< 1, 1,-1> (o + 26624, x1m3, x2m2, t, h);   // 3x2 -> 1 (diff, sgn=+1)
    chunkB           (o + 30720, x1m0, x2m2, t, h);   // 0x2 -> 2
    chunkE<-1, 1, 1> (o + 34816, x1m1, x2m1, t, h);   // 1x1 -> 2 (sum)
    chunkC           (o + 38912, x1m2, x2m0, t, h);   // 2x0 -> 2
    chunkE< 1, 1,-1> (o + 43008, x1m3, x2m1, t, h);   // 3x1 -> 2 (diff, sgn=+1)
    chunkE<-1, 1, 1> (o + 47104, x1m1, x2m2, t, h);   // 1x2 -> 3 (sum)
    chunkE<-1, 1, 1> (o + 51200, x1m2, x2m1, t, h);   // 2x1 -> 3 (sum)
    chunkC           (o + 55296, x1m3, x2m0, t, h);   // 3x0 -> 3
    chunkE<-1, 1, 1> (o + 59392, x1m2, x2m2, t, h);   // 2x2 -> 4 (sum)
    chunkE<-1, 1, 1> (o + 63488, x1m3, x2m1, t, h);   // 3x1 -> 4 (sum)
    chunkE<-1, 1, 1> (o + 67584, x1m3, x2m2, t, h);   // 3x2 -> 5 (sum)
}

} // namespace

extern "C" void kernel_launch(void* const* d_in, const int* in_sizes, int n_in,
                              void* d_out, int out_size) {
    const float* in1 = (const float*)d_in[0];   // (B, 448)
    const float* in2 = (const float*)d_in[1];   // (B, 160)
    float* out = (float*)d_out;                 // (B, 71680)
    const int batch = in_sizes[0] / DIM1;       // 2048
    tp_kernel<<<batch * 2, 256>>>(in1, in2, out);
}

// round 12
// speedup vs baseline: 1.0558x; 1.0558x over previous
#include <cuda_runtime.h>

// ---------------------------------------------------------------------------
// O(2) FullTensorProduct — FINAL: half-row CTAs, 8 CTAs/SM, __stcs stores.
//
// Converged configuration (R8, reproduced R10). 587 MB compulsory output at
// ~6.8 TB/s effective store throughput ≈ 99% of the HW-measured B300 LTS
// chip cap (~6300 B/cyc, path-independent across STG/TMA — so a TMA-store
// rewrite is provably neutral). Full evidence trail:
//   R3  2048x256, 3 waves, .cs        -> 88.3us
//   R4  per-element tiles             -> 114.8us (per-store overhead-bound)
//   R5  single wave, 16 CTA/SM        -> 100.4us (CTA-spread exposure)
//   R6  single wave, 2 rows/CTA       -> 98.8us  (same)
//   R7  half-row CTAs, 7/SM, .cs      -> 86.4us
//   R8  half-row CTAs, 8/SM, .cs      -> 86.2us  <- this kernel (R10: 86.2)
//   R9  R8 with default write-back    -> 90.2us (L2 dirty-drain in replay)
//   R11 R8 with .wt write-through     -> 90.8us (DRAM write serialization)
// Store cache-operator space fully mapped: .cs optimal for streaming stores
// under graph replay.
// ---------------------------------------------------------------------------

namespace {

constexpr int DIM1    = 448;
constexpr int DIM2    = 160;
constexpr int ROW_OUT = 71680;
constexpr float R2f   = 0.70710678118654752440f;   // 1/sqrt(2)
constexpr float SQ2f  = 1.41421356237309504880f;   // sqrt(2)

__device__ __forceinline__ void st4(float* base, int idx4, float4 v) {
    __stcs(reinterpret_cast<float4*>(base) + idx4, v);
}

// kind A: (m=0)x(m=0) -> scalar. 512 float4 total; this CTA does 256.
__device__ __forceinline__ void chunkA(float* o, const float* x1, const float* x2,
                                       int t, int h) {
    int idx = h * 256 + t;               // 0..511
    int u   = idx >> 3;
    int v   = (idx & 7) << 2;
    float a = x1[u];
    st4(o, idx, make_float4(a * x2[v], a * x2[v + 1], a * x2[v + 2], a * x2[v + 3]));
}

// kind B: (m=0)x(m>0). 1024 float4 total; this CTA does 512.
__device__ __forceinline__ void chunkB(float* o, const float* x1, const float* x2,
                                       int t, int h) {
#pragma unroll
    for (int it = 0; it < 2; ++it) {
        int idx = (h * 2 + it) * 256 + t;    // 0..1023
        int u   = idx >> 4;
        int j   = (idx & 15) << 2;
        float a = SQ2f * x1[u];
        st4(o, idx, make_float4(a * x2[j], a * x2[j + 1], a * x2[j + 2], a * x2[j + 3]));
    }
}

// kind C: (m>0)x(m=0). 1024 float4 total; this CTA does 512.
__device__ __forceinline__ void chunkC(float* o, const float* x1, const float* x2,
                                       int t, int h) {
#pragma unroll
    for (int it = 0; it < 2; ++it) {
        int idx = (h * 2 + it) * 256 + t;
        int u   = idx >> 4;
        int j   = (idx & 15) << 1;
        float a = SQ2f * x1[2 * u];
        float b = SQ2f * x1[2 * u + 1];
        float p = x2[j], q = x2[j + 1];
        st4(o, idx, make_float4(a * p, b * p, a * q, b * q));
    }
}

// kind D: (m)x(m) -> m=0. 512 float4 total; this CTA does 256.
template<bool PLUS>
__device__ __forceinline__ void chunkD(float* o, const float* x1, const float* x2,
                                       int t, int h) {
    int idx = h * 256 + t;
    int u   = idx >> 3;
    int j   = idx & 7;
    float c1 = x1[2 * u], s1 = x1[2 * u + 1];
    float r[4];
#pragma unroll
    for (int k = 0; k < 4; ++k) {
        float c2 = x2[8 * j + 2 * k];
        float s2 = x2[8 * j + 2 * k + 1];
        r[k] = PLUS ? R2f * fmaf(c1, c2,  s1 * s2)
                    : R2f * fmaf(s1, c2, -(c1 * s2));
    }
    st4(o, idx, make_float4(r[0], r[1], r[2], r[3]));
}

// kind E: (m1)x(m2) -> 2-dim irrep. 1024 float4 total; this CTA does 512.
template<int SA, int SSC, int SCS>
__device__ __forceinline__ void chunkE(float* o, const float* x1, const float* x2,
                                       int t, int h) {
#pragma unroll
    for (int it = 0; it < 2; ++it) {
        int idx = (h * 2 + it) * 256 + t;
        int u   = idx >> 4;
        int j   = idx & 15;
        float c1 = x1[2 * u], s1 = x1[2 * u + 1];
        float4 r;
        {
            float c2 = x2[4 * j], s2 = x2[4 * j + 1];
            r.x = fmaf(c1, c2, float(SA) * (s1 * s2));
            r.y = fmaf(float(SSC) * s1, c2, float(SCS) * (c1 * s2));
        }
        {
            float c2 = x2[4 * j + 2], s2 = x2[4 * j + 3];
            r.z = fmaf(c1, c2, float(SA) * (s1 * s2));
            r.w = fmaf(float(SSC) * s1, c2, float(SCS) * (c1 * s2));
        }
        st4(o, idx, r);
    }
}

__global__ void __launch_bounds__(256, 8) tp_kernel(const float* __restrict__ in1,
                                                    const float* __restrict__ in2,
                                                    float* __restrict__ out) {
    __shared__ __align__(16) float s1[DIM1];
    __shared__ __align__(16) float s2[DIM2];

    const int t = threadIdx.x;                 // 0..255
    const unsigned bid = blockIdx.x;           // 0..4095
    const size_t b = bid >> 1;                 // batch row
    const int    h = bid & 1;                  // which half of the row

    const float4* r1 = reinterpret_cast<const float4*>(in1 + b * DIM1);
    const float4* r2 = reinterpret_cast<const float4*>(in2 + b * DIM2);
    if (t < 112) reinterpret_cast<float4*>(s1)[t] = r1[t];
    if (t < 40)  reinterpret_cast<float4*>(s2)[t] = r2[t];
    __syncthreads();

    float* o = out + b * (size_t)ROW_OUT;

    const float* x1m0 = s1;          // [0,64)
    const float* x1m1 = s1 + 64;     // [64,192)
    const float* x1m2 = s1 + 192;    // [192,320)
    const float* x1m3 = s1 + 320;    // [320,448)
    const float* x2m0 = s2;          // [0,32)
    const float* x2m1 = s2 + 32;     // [32,96)
    const float* x2m2 = s2 + 96;     // [96,160)

    // Output chunks in INV (irrep-sorted, stable) order; offsets in floats.
    chunkA           (o + 0,     x1m0, x2m0, t, h);   // 0x0 -> 0+
    chunkD<true >    (o + 2048,  x1m1, x2m1, t, h);   // 1x1 -> 0+
    chunkD<true >    (o + 4096,  x1m2, x2m2, t, h);   // 2x2 -> 0+
    chunkD<false>    (o + 6144,  x1m1, x2m1, t, h);   // 1x1 -> 0-
    chunkD<false>    (o + 8192,  x1m2, x2m2, t, h);   // 2x2 -> 0-
    chunkB           (o + 10240, x1m0, x2m1, t, h);   // 0x1 -> 1
    chunkC           (o + 14336, x1m1, x2m0, t, h);   // 1x0 -> 1
    chunkE< 1,-1, 1> (o + 18432, x1m1, x2m2, t, h);   // 1x2 -> 1 (diff, sgn=-1)
    chunkE< 1, 1,-1> (o + 22528, x1m2, x2m1, t, h);   // 2x1 -> 1 (diff, sgn=+1)
    chunkE< 1, 1,-1> (o + 26624, x1m3, x2m2, t, h);   // 3x2 -> 1 (diff, sgn=+1)
    chunkB           (o + 30720, x1m0, x2m2, t, h);   // 0x2 -> 2
    chunkE<-1, 1, 1> (o + 34816, x1m1, x2m1, t, h);   // 1x1 -> 2 (sum)
    chunkC           (o + 38912, x1m2, x2m0, t, h);   // 2x0 -> 2
    chunkE< 1, 1,-1> (o + 43008, x1m3, x2m1, t, h);   // 3x1 -> 2 (diff, sgn=+1)
    chunkE<-1, 1, 1> (o + 47104, x1m1, x2m2, t, h);   // 1x2 -> 3 (sum)
    chunkE<-1, 1, 1> (o + 51200, x1m2, x2m1, t, h);   // 2x1 -> 3 (sum)
    chunkC           (o + 55296, x1m3, x2m0, t, h);   // 3x0 -> 3
    chunkE<-1, 1, 1> (o + 59392, x1m2, x2m2, t, h);   // 2x2 -> 4 (sum)
    chunkE<-1, 1, 1> (o + 63488, x1m3, x2m1, t, h);   // 3x1 -> 4 (sum)
    chunkE<-1, 1, 1> (o + 67584, x1m3, x2m2, t, h);   // 3x2 -> 5 (sum)
}

} // namespace

extern "C" void kernel_launch(void* const* d_in, const int* in_sizes, int n_in,
                              void* d_out, int out_size) {
    const float* in1 = (const float*)d_in[0];   // (B, 448)
    const float* in2 = (const float*)d_in[1];   // (B, 160)
    float* out = (float*)d_out;                 // (B, 71680)
    const int batch = in_sizes[0] / DIM1;       // 2048
    tp_kernel<<<batch * 2, 256>>>(in1, in2, out);
}